// round 1
// baseline (speedup 1.0000x reference)
#include <cuda_runtime.h>
#include <math.h>

#define PP 7
#define NDIR 49
#define KDIM 147
#define KP 152           // padded K (multiple of 8, float4-aligned rows)
#define NPATCH 65536     // 64 * 32 * 32
#define EOUT 384
#define HW 224

// Scratch (device globals: allocation-free rule)
__device__ __align__(16) float g_S[(size_t)NPATCH * KP];   // sampled patches, padded
__device__ __align__(16) float g_Wt[KP * EOUT];            // proj_w^T, padded rows zeroed
__device__ float g_u0[NDIR], g_u1[NDIR], g_sv[NDIR];

__device__ __forceinline__ float sigf(float v) { return 1.0f / (1.0f + expf(-v)); }

// ---------------- init: direction table ----------------
__global__ void init_dirs_kernel() {
    int n = threadIdx.x;
    if (n >= NDIR) return;
    float u0, u1, sv;
    if (n == 0) { u0 = 1.f; u1 = 0.f; sv = 0.f; }
    else {
        int k, nk, m;
        if (n < 9)       { k = 1; nk = 8;  m = n - 1;  }
        else if (n < 25) { k = 2; nk = 16; m = n - 9;  }
        else             { k = 3; nk = 24; m = n - 25; }
        double th = 2.0 * 3.14159265358979323846 * (double)m / (double)nk;
        u0 = (float)cos(th);
        u1 = (float)sin(th);
        sv = (float)((double)k / 3.0);
    }
    g_u0[n] = u0; g_u1[n] = u1; g_sv[n] = sv;
}

// ---------------- prep: transpose proj_w into padded Wt ----------------
__global__ void wt_kernel(const float* __restrict__ pw) {
    int idx = blockIdx.x * blockDim.x + threadIdx.x;
    if (idx >= KP * EOUT) return;
    int k = idx / EOUT, e = idx % EOUT;
    g_Wt[idx] = (k < KDIM) ? pw[e * KDIM + k] : 0.0f;
}

// ---------------- stage A: params + sampling ----------------
// 8 patches per block (1 warp each), 256 threads
__global__ __launch_bounds__(256) void sample_kernel(
    const float* __restrict__ x, const float* __restrict__ mw, const float* __restrict__ mb)
{
    __shared__ float s_w[7 * KDIM];      // metric_w
    __shared__ float s_px[8][KDIM + 1];  // patch pixels
    __shared__ float s_d[8][8];          // derived params per patch

    int t = threadIdx.x;
    for (int i = t; i < 7 * KDIM; i += 256) s_w[i] = mw[i];

    int warp = t >> 5, lane = t & 31;
    int p = blockIdx.x * 8 + warp;
    int b  = p >> 10;
    int rem = p & 1023;
    int hp = rem >> 5, wp = rem & 31;
    const float* xb = x + (size_t)b * 3 * HW * HW;

    // load patch pixels (k = c*49 + i*7 + j)
    for (int idx = lane; idx < KDIM; idx += 32) {
        int c = idx / 49, r2 = idx % 49, i = r2 / 7, j = r2 % 7;
        s_px[warp][idx] = __ldg(xb + ((size_t)c * HW + hp * 7 + i) * HW + wp * 7 + j);
    }
    __syncthreads();

    // 7-filter conv (warp-parallel partial sums + shfl reduce)
    float acc[7] = {0.f,0.f,0.f,0.f,0.f,0.f,0.f};
    for (int idx = lane; idx < KDIM; idx += 32) {
        float v = s_px[warp][idx];
        #pragma unroll
        for (int f = 0; f < 7; f++) acc[f] += v * s_w[f * KDIM + idx];
    }
    #pragma unroll
    for (int f = 0; f < 7; f++) {
        #pragma unroll
        for (int off = 16; off > 0; off >>= 1)
            acc[f] += __shfl_down_sync(0xffffffffu, acc[f], off);
    }

    if (lane == 0) {
        float q0 = acc[0] + __ldg(mb + 0);
        float q1 = acc[1] + __ldg(mb + 1);
        float q2 = acc[2] + __ldg(mb + 2);
        float q3 = acc[3] + __ldg(mb + 3);
        float q4 = acc[4] + __ldg(mb + 4);
        float q5 = acc[5] + __ldg(mb + 5);
        float q6 = acc[6] + __ldg(mb + 6);
        float nrm = fmaxf(sqrtf(q0*q0 + q1*q1), 1e-12f);
        float v0 = q0 / nrm, v1 = q1 / nrm;
        float sc = 0.5f + 1.5f * sigf(q4);
        float e0 = 2.0f * sigf(q2) * sc;
        float e1 = 2.0f * sigf(q3) * sc;
        float m00 = e0 * v0 * v0 + e1 * v1 * v1;
        float m01 = (e0 - e1) * v0 * v1;
        float m11 = e0 * v1 * v1 + e1 * v0 * v0;
        float wn = sqrtf(q5*q5 + q6*q6);
        float ws = 0.5f * sigf(wn);
        s_d[warp][0] = m00; s_d[warp][1] = m01; s_d[warp][2] = m11;
        s_d[warp][3] = q5 * ws; s_d[warp][4] = q6 * ws;
    }
    __syncwarp();

    float m00 = s_d[warp][0], m01 = s_d[warp][1], m11 = s_d[warp][2];
    float w0 = s_d[warp][3], w1 = s_d[warp][4];
    float cy = (float)(hp * 7 + 3);
    float cx = (float)(wp * 7 + 3);
    size_t rbase = (size_t)p * KP;

    for (int n = lane; n < NDIR; n += 32) {
        float u0 = g_u0[n], u1 = g_u1[n], sv = g_sv[n];
        float quad = u0*u0*m00 + 2.0f*u0*u1*m01 + u1*u1*m11;
        float F = sqrtf(quad + 1e-6f) + w0 * u0 + w1 * u1;
        float tt = sv / (F + 1e-6f);
        float py = u1 * tt + cy;
        float px = u0 * tt + cx;
        float y0 = floorf(py), x0 = floorf(px);
        float wy = py - y0, wx = px - x0;

        float s0 = 0.f, s1 = 0.f, s2 = 0.f;
        #pragma unroll
        for (int corner = 0; corner < 4; corner++) {
            float yf = y0 + (float)(corner >> 1);
            float xf = x0 + (float)(corner & 1);
            float wgt = ((corner >> 1) ? wy : (1.0f - wy)) * ((corner & 1) ? wx : (1.0f - wx));
            bool valid = (yf >= 0.f) && (yf <= 223.f) && (xf >= 0.f) && (xf <= 223.f);
            if (valid) {
                int yi = (int)yf, xi = (int)xf;
                const float* ptr = xb + (size_t)yi * HW + xi;
                s0 += wgt * __ldg(ptr);
                s1 += wgt * __ldg(ptr + HW * HW);
                s2 += wgt * __ldg(ptr + 2 * HW * HW);
            }
        }
        g_S[rbase + 0 * 49 + n] = s0;
        g_S[rbase + 1 * 49 + n] = s1;
        g_S[rbase + 2 * 49 + n] = s2;
    }
    if (lane < KP - KDIM) g_S[rbase + KDIM + lane] = 0.0f;  // zero pad cols
}

// ---------------- stage B: SGEMM 65536x152 @ 152x384 + bias ----------------
#define GBM 128
#define GBN 128
#define GBK 8
__global__ __launch_bounds__(256) void gemm_kernel(
    const float* __restrict__ bias, float* __restrict__ out)
{
    __shared__ float As[GBK][GBM];
    __shared__ float Bs[GBK][GBN];

    int t = threadIdx.x;
    int bm = blockIdx.y * GBM;
    int bn = blockIdx.x * GBN;
    int tx = t & 15, ty = t >> 4;

    int arow = t >> 1;
    int acol4 = (t & 1) * 4;
    int brow = t >> 5;
    int bcol4 = (t & 31) * 4;

    const float* Aptr = g_S + (size_t)(bm + arow) * KP + acol4;
    const float* Bptr = g_Wt + (size_t)brow * EOUT + bn + bcol4;

    float accv[8][8];
    #pragma unroll
    for (int i = 0; i < 8; i++)
        #pragma unroll
        for (int j = 0; j < 8; j++) accv[i][j] = 0.0f;

    for (int k0 = 0; k0 < KP; k0 += GBK) {
        float4 av = *(const float4*)(Aptr + k0);
        float4 bv = *(const float4*)(Bptr + (size_t)k0 * EOUT);
        As[acol4 + 0][arow] = av.x;
        As[acol4 + 1][arow] = av.y;
        As[acol4 + 2][arow] = av.z;
        As[acol4 + 3][arow] = av.w;
        *(float4*)&Bs[brow][bcol4] = bv;
        __syncthreads();

        #pragma unroll
        for (int kk = 0; kk < GBK; kk++) {
            float4 a0 = *(const float4*)&As[kk][ty * 8];
            float4 a1 = *(const float4*)&As[kk][ty * 8 + 4];
            float4 b0 = *(const float4*)&Bs[kk][tx * 8];
            float4 b1 = *(const float4*)&Bs[kk][tx * 8 + 4];
            float a[8] = {a0.x, a0.y, a0.z, a0.w, a1.x, a1.y, a1.z, a1.w};
            float bb[8] = {b0.x, b0.y, b0.z, b0.w, b1.x, b1.y, b1.z, b1.w};
            #pragma unroll
            for (int i = 0; i < 8; i++)
                #pragma unroll
                for (int j = 0; j < 8; j++) accv[i][j] += a[i] * bb[j];
        }
        __syncthreads();
    }

    float bvals[8];
    #pragma unroll
    for (int j = 0; j < 8; j++) bvals[j] = __ldg(bias + bn + tx * 8 + j);
    #pragma unroll
    for (int i = 0; i < 8; i++) {
        float* orow = out + (size_t)(bm + ty * 8 + i) * EOUT + bn + tx * 8;
        #pragma unroll
        for (int j = 0; j < 8; j++) orow[j] = accv[i][j] + bvals[j];
    }
}

extern "C" void kernel_launch(void* const* d_in, const int* in_sizes, int n_in,
                              void* d_out, int out_size)
{
    const float* x  = (const float*)d_in[0];
    const float* mw = (const float*)d_in[1];
    const float* mb = (const float*)d_in[2];
    const float* pw = (const float*)d_in[3];
    const float* pb = (const float*)d_in[4];
    float* out = (float*)d_out;

    init_dirs_kernel<<<1, 64>>>();
    wt_kernel<<<(KP * EOUT + 255) / 256, 256>>>(pw);
    sample_kernel<<<NPATCH / 8, 256>>>(x, mw, mb);
    gemm_kernel<<<dim3(EOUT / GBN, NPATCH / GBM), 256>>>(pb, out);
}

// round 2
// speedup vs baseline: 1.2141x; 1.2141x over previous
#include <cuda_runtime.h>
#include <math.h>

#define PP 7
#define NDIR 49
#define KDIM 147
#define KP 152           // padded K (multiple of 8, float4-aligned rows)
#define NPATCH 65536     // 64 * 32 * 32
#define EOUT 384
#define HW 224

// Scratch (device globals: allocation-free rule)
__device__ __align__(16) float g_S[(size_t)NPATCH * KP];   // sampled patches, padded
__device__ __align__(16) float g_Wt[KP * EOUT];            // proj_w^T, padded rows zeroed
__device__ float g_u0[NDIR], g_u1[NDIR], g_sv[NDIR];

__device__ __forceinline__ float sigf(float v) { return 1.0f / (1.0f + expf(-v)); }

// packed f32x2 helpers (Blackwell FFMA2 path)
__device__ __forceinline__ unsigned long long pack2(float lo, float hi) {
    unsigned long long r;
    asm("mov.b64 %0, {%1, %2};" : "=l"(r) : "f"(lo), "f"(hi));
    return r;
}
__device__ __forceinline__ void fma2(unsigned long long& d, unsigned long long a,
                                     unsigned long long b) {
    asm("fma.rn.f32x2 %0, %1, %2, %3;" : "=l"(d) : "l"(a), "l"(b), "l"(d));
}
__device__ __forceinline__ void unpack2(unsigned long long v, float& lo, float& hi) {
    asm("mov.b64 {%0, %1}, %2;" : "=f"(lo), "=f"(hi) : "l"(v));
}

// ---------------- init: direction table ----------------
__global__ void init_dirs_kernel() {
    int n = threadIdx.x;
    if (n >= NDIR) return;
    float u0, u1, sv;
    if (n == 0) { u0 = 1.f; u1 = 0.f; sv = 0.f; }
    else {
        int k, nk, m;
        if (n < 9)       { k = 1; nk = 8;  m = n - 1;  }
        else if (n < 25) { k = 2; nk = 16; m = n - 9;  }
        else             { k = 3; nk = 24; m = n - 25; }
        double th = 2.0 * 3.14159265358979323846 * (double)m / (double)nk;
        u0 = (float)cos(th);
        u1 = (float)sin(th);
        sv = (float)((double)k / 3.0);
    }
    g_u0[n] = u0; g_u1[n] = u1; g_sv[n] = sv;
}

// ---------------- prep: transpose proj_w into padded Wt ----------------
__global__ void wt_kernel(const float* __restrict__ pw) {
    int idx = blockIdx.x * blockDim.x + threadIdx.x;
    if (idx >= KP * EOUT) return;
    int k = idx / EOUT, e = idx % EOUT;
    g_Wt[idx] = (k < KDIM) ? pw[e * KDIM + k] : 0.0f;
}

// ---------------- stage A: params + sampling ----------------
// 8 patches per block (1 warp each), 256 threads
__global__ __launch_bounds__(256) void sample_kernel(
    const float* __restrict__ x, const float* __restrict__ mw, const float* __restrict__ mb)
{
    __shared__ float s_w[7 * KDIM];      // metric_w
    __shared__ float s_px[8][KDIM + 1];  // patch pixels
    __shared__ float s_d[8][8];          // derived params per patch

    int t = threadIdx.x;
    for (int i = t; i < 7 * KDIM; i += 256) s_w[i] = mw[i];

    int warp = t >> 5, lane = t & 31;
    int p = blockIdx.x * 8 + warp;
    int b  = p >> 10;
    int rem = p & 1023;
    int hp = rem >> 5, wp = rem & 31;
    const float* xb = x + (size_t)b * 3 * HW * HW;

    // load patch pixels (k = c*49 + i*7 + j)
    for (int idx = lane; idx < KDIM; idx += 32) {
        int c = idx / 49, r2 = idx % 49, i = r2 / 7, j = r2 % 7;
        s_px[warp][idx] = __ldg(xb + ((size_t)c * HW + hp * 7 + i) * HW + wp * 7 + j);
    }
    __syncthreads();

    // 7-filter conv (warp-parallel partial sums + shfl reduce)
    float acc[7] = {0.f,0.f,0.f,0.f,0.f,0.f,0.f};
    for (int idx = lane; idx < KDIM; idx += 32) {
        float v = s_px[warp][idx];
        #pragma unroll
        for (int f = 0; f < 7; f++) acc[f] += v * s_w[f * KDIM + idx];
    }
    #pragma unroll
    for (int f = 0; f < 7; f++) {
        #pragma unroll
        for (int off = 16; off > 0; off >>= 1)
            acc[f] += __shfl_down_sync(0xffffffffu, acc[f], off);
    }

    if (lane == 0) {
        float q0 = acc[0] + __ldg(mb + 0);
        float q1 = acc[1] + __ldg(mb + 1);
        float q2 = acc[2] + __ldg(mb + 2);
        float q3 = acc[3] + __ldg(mb + 3);
        float q4 = acc[4] + __ldg(mb + 4);
        float q5 = acc[5] + __ldg(mb + 5);
        float q6 = acc[6] + __ldg(mb + 6);
        float nrm = fmaxf(sqrtf(q0*q0 + q1*q1), 1e-12f);
        float v0 = q0 / nrm, v1 = q1 / nrm;
        float sc = 0.5f + 1.5f * sigf(q4);
        float e0 = 2.0f * sigf(q2) * sc;
        float e1 = 2.0f * sigf(q3) * sc;
        float m00 = e0 * v0 * v0 + e1 * v1 * v1;
        float m01 = (e0 - e1) * v0 * v1;
        float m11 = e0 * v1 * v1 + e1 * v0 * v0;
        float wn = sqrtf(q5*q5 + q6*q6);
        float ws = 0.5f * sigf(wn);
        s_d[warp][0] = m00; s_d[warp][1] = m01; s_d[warp][2] = m11;
        s_d[warp][3] = q5 * ws; s_d[warp][4] = q6 * ws;
    }
    __syncwarp();

    float m00 = s_d[warp][0], m01 = s_d[warp][1], m11 = s_d[warp][2];
    float w0 = s_d[warp][3], w1 = s_d[warp][4];
    float cy = (float)(hp * 7 + 3);
    float cx = (float)(wp * 7 + 3);
    size_t rbase = (size_t)p * KP;

    for (int n = lane; n < NDIR; n += 32) {
        float u0 = g_u0[n], u1 = g_u1[n], sv = g_sv[n];
        float quad = u0*u0*m00 + 2.0f*u0*u1*m01 + u1*u1*m11;
        float F = sqrtf(quad + 1e-6f) + w0 * u0 + w1 * u1;
        float tt = sv / (F + 1e-6f);
        float py = u1 * tt + cy;
        float px = u0 * tt + cx;
        float y0 = floorf(py), x0 = floorf(px);
        float wy = py - y0, wx = px - x0;

        float s0 = 0.f, s1 = 0.f, s2 = 0.f;
        #pragma unroll
        for (int corner = 0; corner < 4; corner++) {
            float yf = y0 + (float)(corner >> 1);
            float xf = x0 + (float)(corner & 1);
            float wgt = ((corner >> 1) ? wy : (1.0f - wy)) * ((corner & 1) ? wx : (1.0f - wx));
            bool valid = (yf >= 0.f) && (yf <= 223.f) && (xf >= 0.f) && (xf <= 223.f);
            if (valid) {
                int yi = (int)yf, xi = (int)xf;
                const float* ptr = xb + (size_t)yi * HW + xi;
                s0 += wgt * __ldg(ptr);
                s1 += wgt * __ldg(ptr + HW * HW);
                s2 += wgt * __ldg(ptr + 2 * HW * HW);
            }
        }
        g_S[rbase + 0 * 49 + n] = s0;
        g_S[rbase + 1 * 49 + n] = s1;
        g_S[rbase + 2 * 49 + n] = s2;
    }
    if (lane < KP - KDIM) g_S[rbase + KDIM + lane] = 0.0f;  // zero pad cols
}

// ---------------- stage B: SGEMM 65536x152 @ 152x384 + bias (FFMA2 path) ----
#define GBM 128
#define GBN 128
#define GBK 8
__global__ __launch_bounds__(256) void gemm_kernel(
    const float* __restrict__ bias, float* __restrict__ out)
{
    __shared__ float As[GBK][GBM];
    __shared__ __align__(16) float Bs[GBK][GBN];

    int t = threadIdx.x;
    int bm = blockIdx.y * GBM;
    int bn = blockIdx.x * GBN;
    int tx = t & 15, ty = t >> 4;

    int arow = t >> 1;
    int acol4 = (t & 1) * 4;
    int brow = t >> 5;
    int bcol4 = (t & 31) * 4;

    const float* Aptr = g_S + (size_t)(bm + arow) * KP + acol4;
    const float* Bptr = g_Wt + (size_t)brow * EOUT + bn + bcol4;

    // 8 rows x 4 packed col-pairs of f32x2 accumulators
    unsigned long long acc[8][4];
    #pragma unroll
    for (int i = 0; i < 8; i++)
        #pragma unroll
        for (int j = 0; j < 4; j++) acc[i][j] = 0ull;

    for (int k0 = 0; k0 < KP; k0 += GBK) {
        float4 av = *(const float4*)(Aptr + k0);
        float4 bv = *(const float4*)(Bptr + (size_t)k0 * EOUT);
        As[acol4 + 0][arow] = av.x;
        As[acol4 + 1][arow] = av.y;
        As[acol4 + 2][arow] = av.z;
        As[acol4 + 3][arow] = av.w;
        *(float4*)&Bs[brow][bcol4] = bv;
        __syncthreads();

        #pragma unroll
        for (int kk = 0; kk < GBK; kk++) {
            float4 a0 = *(const float4*)&As[kk][ty * 8];
            float4 a1 = *(const float4*)&As[kk][ty * 8 + 4];
            // B pairs straight from shared as packed 64-bit lanes
            const unsigned long long* bp =
                (const unsigned long long*)&Bs[kk][tx * 8];
            unsigned long long b0 = bp[0], b1 = bp[1], b2 = bp[2], b3 = bp[3];
            float a[8] = {a0.x, a0.y, a0.z, a0.w, a1.x, a1.y, a1.z, a1.w};
            #pragma unroll
            for (int i = 0; i < 8; i++) {
                unsigned long long ad = pack2(a[i], a[i]);
                fma2(acc[i][0], ad, b0);
                fma2(acc[i][1], ad, b1);
                fma2(acc[i][2], ad, b2);
                fma2(acc[i][3], ad, b3);
            }
        }
        __syncthreads();
    }

    float bvals[8];
    #pragma unroll
    for (int j = 0; j < 8; j++) bvals[j] = __ldg(bias + bn + tx * 8 + j);
    #pragma unroll
    for (int i = 0; i < 8; i++) {
        float r[8];
        #pragma unroll
        for (int j = 0; j < 4; j++) unpack2(acc[i][j], r[2 * j], r[2 * j + 1]);
        float4 o0, o1;
        o0.x = r[0] + bvals[0]; o0.y = r[1] + bvals[1];
        o0.z = r[2] + bvals[2]; o0.w = r[3] + bvals[3];
        o1.x = r[4] + bvals[4]; o1.y = r[5] + bvals[5];
        o1.z = r[6] + bvals[6]; o1.w = r[7] + bvals[7];
        float* orow = out + (size_t)(bm + ty * 8 + i) * EOUT + bn + tx * 8;
        *(float4*)orow = o0;
        *(float4*)(orow + 4) = o1;
    }
}

extern "C" void kernel_launch(void* const* d_in, const int* in_sizes, int n_in,
                              void* d_out, int out_size)
{
    const float* x  = (const float*)d_in[0];
    const float* mw = (const float*)d_in[1];
    const float* mb = (const float*)d_in[2];
    const float* pw = (const float*)d_in[3];
    const float* pb = (const float*)d_in[4];
    float* out = (float*)d_out;

    init_dirs_kernel<<<1, 64>>>();
    wt_kernel<<<(KP * EOUT + 255) / 256, 256>>>(pw);
    sample_kernel<<<NPATCH / 8, 256>>>(x, mw, mb);
    gemm_kernel<<<dim3(EOUT / GBN, NPATCH / GBM), 256>>>(pb, out);
}

// round 5
// speedup vs baseline: 1.8922x; 1.5585x over previous
#include <cuda_runtime.h>
#include <cuda_bf16.h>
#include <math.h>
#include <stdint.h>

#define NDIR 49
#define KDIM 147
#define KP 160            // K padded to 5 x 32 chunks
#define NPATCH 65536      // 64 * 32 * 32
#define EOUT 384
#define HW 224
#define MT 128
#define NT 128
#define NMT (NPATCH / MT) // 512
#define KCH 32
#define NCHUNK (KP / KCH) // 5

// SMEM layout (bytes)
#define AS_STRIDE 80                 // 40 bf16 per A row (conflict-free ldmatrix)
#define AS_SIZE   (128 * AS_STRIDE)  // 10240 per (buf,hl)
#define BS_STRIDE 272                // 136 bf16 per B k-row (128 data + pad)
#define BS_SIZE   (KP * BS_STRIDE)   // 43520 per hl
#define SM_A      0                  // [buf2][hl2] -> 40960
#define SM_B      40960              // [hl2] -> 87040
#define SM_BIAS   128000             // 512
#define SMEM_TOTAL 128512

// ---- scratch ----
__device__ __align__(16) __nv_bfloat16 g_Sh[(size_t)NPATCH * KP];
__device__ __align__(16) __nv_bfloat16 g_Sl[(size_t)NPATCH * KP];
__device__ __align__(16) __nv_bfloat16 g_Bh[KP * EOUT];  // [k][e]
__device__ __align__(16) __nv_bfloat16 g_Bl[KP * EOUT];
__device__ float g_u0[NDIR], g_u1[NDIR], g_sv[NDIR];

__device__ __forceinline__ float sigf(float v) { return 1.0f / (1.0f + expf(-v)); }

__device__ __forceinline__ uint32_t smem_u32(const void* p) {
    uint32_t a;
    asm("{ .reg .u64 t; cvta.to.shared.u64 t, %1; cvt.u32.u64 %0, t; }" : "=r"(a) : "l"(p));
    return a;
}

#define LDSM_X4(r, addr) \
    asm volatile("ldmatrix.sync.aligned.m8n8.x4.shared.b16 {%0,%1,%2,%3}, [%4];" \
        : "=r"((r)[0]), "=r"((r)[1]), "=r"((r)[2]), "=r"((r)[3]) : "r"(addr))

#define LDSM_X4_T(r, addr) \
    asm volatile("ldmatrix.sync.aligned.m8n8.x4.trans.shared.b16 {%0,%1,%2,%3}, [%4];" \
        : "=r"((r)[0]), "=r"((r)[1]), "=r"((r)[2]), "=r"((r)[3]) : "r"(addr))

#define MMA_BF16(d, a, b0, b1) \
    asm volatile("mma.sync.aligned.m16n8k16.row.col.f32.bf16.bf16.f32 " \
        "{%0,%1,%2,%3}, {%4,%5,%6,%7}, {%8,%9}, {%0,%1,%2,%3};" \
        : "+f"((d)[0]), "+f"((d)[1]), "+f"((d)[2]), "+f"((d)[3]) \
        : "r"((a)[0]), "r"((a)[1]), "r"((a)[2]), "r"((a)[3]), "r"(b0), "r"(b1))

__device__ __forceinline__ void split_bf(float v, __nv_bfloat16& h, __nv_bfloat16& l) {
    h = __float2bfloat16_rn(v);
    l = __float2bfloat16_rn(v - __bfloat162float(h));
}

// ---------------- init: direction table ----------------
__global__ void init_dirs_kernel() {
    int n = threadIdx.x;
    if (n >= NDIR) return;
    float u0, u1, sv;
    if (n == 0) { u0 = 1.f; u1 = 0.f; sv = 0.f; }
    else {
        int k, nk, m;
        if (n < 9)       { k = 1; nk = 8;  m = n - 1;  }
        else if (n < 25) { k = 2; nk = 16; m = n - 9;  }
        else             { k = 3; nk = 24; m = n - 25; }
        double th = 2.0 * 3.14159265358979323846 * (double)m / (double)nk;
        u0 = (float)cos(th); u1 = (float)sin(th);
        sv = (float)((double)k / 3.0);
    }
    g_u0[n] = u0; g_u1[n] = u1; g_sv[n] = sv;
}

// -------- prep: proj_w -> transposed, padded, hi/lo bf16 [k][e] --------
__global__ void bfill_kernel(const float* __restrict__ pw) {
    int idx = blockIdx.x * blockDim.x + threadIdx.x;
    if (idx >= KP * EOUT) return;
    int k = idx / EOUT, e = idx % EOUT;
    float v = (k < KDIM) ? pw[e * KDIM + k] : 0.0f;
    __nv_bfloat16 h, l;
    split_bf(v, h, l);
    g_Bh[idx] = h;
    g_Bl[idx] = l;
}

// ---------------- stage A: params + sampling ----------------
__global__ __launch_bounds__(256) void sample_kernel(
    const float* __restrict__ x, const float* __restrict__ mw, const float* __restrict__ mb)
{
    __shared__ float s_w[7 * KDIM];
    __shared__ float s_px[8][KDIM + 1];
    __shared__ float s_d[8][8];

    int t = threadIdx.x;
    for (int i = t; i < 7 * KDIM; i += 256) s_w[i] = mw[i];

    int warp = t >> 5, lane = t & 31;
    int p = blockIdx.x * 8 + warp;
    int b = p >> 10;
    int rem = p & 1023;
    int hp = rem >> 5, wp = rem & 31;
    const float* xb = x + (size_t)b * 3 * HW * HW;

    for (int idx = lane; idx < KDIM; idx += 32) {
        int c = idx / 49, r2 = idx % 49, i = r2 / 7, j = r2 % 7;
        s_px[warp][idx] = __ldg(xb + ((size_t)c * HW + hp * 7 + i) * HW + wp * 7 + j);
    }
    __syncthreads();

    float acc[7] = {0.f,0.f,0.f,0.f,0.f,0.f,0.f};
    for (int idx = lane; idx < KDIM; idx += 32) {
        float v = s_px[warp][idx];
        #pragma unroll
        for (int f = 0; f < 7; f++) acc[f] += v * s_w[f * KDIM + idx];
    }
    #pragma unroll
    for (int f = 0; f < 7; f++) {
        #pragma unroll
        for (int off = 16; off > 0; off >>= 1)
            acc[f] += __shfl_down_sync(0xffffffffu, acc[f], off);
    }

    if (lane == 0) {
        float q0 = acc[0] + __ldg(mb + 0);
        float q1 = acc[1] + __ldg(mb + 1);
        float q2 = acc[2] + __ldg(mb + 2);
        float q3 = acc[3] + __ldg(mb + 3);
        float q4 = acc[4] + __ldg(mb + 4);
        float q5 = acc[5] + __ldg(mb + 5);
        float q6 = acc[6] + __ldg(mb + 6);
        float nrm = fmaxf(sqrtf(q0*q0 + q1*q1), 1e-12f);
        float v0 = q0 / nrm, v1 = q1 / nrm;
        float sc = 0.5f + 1.5f * sigf(q4);
        float e0 = 2.0f * sigf(q2) * sc;
        float e1 = 2.0f * sigf(q3) * sc;
        float m00 = e0 * v0 * v0 + e1 * v1 * v1;
        float m01 = (e0 - e1) * v0 * v1;
        float m11 = e0 * v1 * v1 + e1 * v0 * v0;
        float wn = sqrtf(q5*q5 + q6*q6);
        float ws = 0.5f * sigf(wn);
        s_d[warp][0] = m00; s_d[warp][1] = m01; s_d[warp][2] = m11;
        s_d[warp][3] = q5 * ws; s_d[warp][4] = q6 * ws;
    }
    __syncwarp();

    float m00 = s_d[warp][0], m01 = s_d[warp][1], m11 = s_d[warp][2];
    float w0 = s_d[warp][3], w1 = s_d[warp][4];
    float cy = (float)(hp * 7 + 3);
    float cx = (float)(wp * 7 + 3);
    size_t rbase = (size_t)p * KP;

    for (int n = lane; n < NDIR; n += 32) {
        float u0 = g_u0[n], u1 = g_u1[n], sv = g_sv[n];
        float quad = u0*u0*m00 + 2.0f*u0*u1*m01 + u1*u1*m11;
        float F = sqrtf(quad + 1e-6f) + w0 * u0 + w1 * u1;
        float tt = sv / (F + 1e-6f);
        float py = u1 * tt + cy;
        float px = u0 * tt + cx;
        float y0 = floorf(py), x0 = floorf(px);
        float wy = py - y0, wx = px - x0;

        float s0 = 0.f, s1 = 0.f, s2 = 0.f;
        #pragma unroll
        for (int corner = 0; corner < 4; corner++) {
            float yf = y0 + (float)(corner >> 1);
            float xf = x0 + (float)(corner & 1);
            float wgt = ((corner >> 1) ? wy : (1.0f - wy)) * ((corner & 1) ? wx : (1.0f - wx));
            bool valid = (yf >= 0.f) && (yf <= 223.f) && (xf >= 0.f) && (xf <= 223.f);
            if (valid) {
                int yi = (int)yf, xi = (int)xf;
                const float* ptr = xb + (size_t)yi * HW + xi;
                s0 += wgt * __ldg(ptr);
                s1 += wgt * __ldg(ptr + HW * HW);
                s2 += wgt * __ldg(ptr + 2 * HW * HW);
            }
        }
        __nv_bfloat16 h, l;
        split_bf(s0, h, l); g_Sh[rbase + 0 * 49 + n] = h; g_Sl[rbase + 0 * 49 + n] = l;
        split_bf(s1, h, l); g_Sh[rbase + 1 * 49 + n] = h; g_Sl[rbase + 1 * 49 + n] = l;
        split_bf(s2, h, l); g_Sh[rbase + 2 * 49 + n] = h; g_Sl[rbase + 2 * 49 + n] = l;
    }
    if (lane < KP - KDIM) {
        g_Sh[rbase + KDIM + lane] = __float2bfloat16(0.0f);
        g_Sl[rbase + KDIM + lane] = __float2bfloat16(0.0f);
    }
}

// ---------------- stage B: bf16 mma.sync 3-product GEMM ----------------
__global__ void __launch_bounds__(256, 1)
gemm_mma(const float* __restrict__ pb, float* __restrict__ out)
{
    extern __shared__ __align__(16) char smem[];
    uint32_t sb = smem_u32(smem);
    int tid = threadIdx.x, wid = tid >> 5, lane = tid & 31;
    int warp_m = wid & 3, warp_n = wid >> 2;
    int bm = blockIdx.x * MT;
    int bn = blockIdx.y * NT;

    // bias to smem
    if (tid < NT) *(float*)(smem + SM_BIAS + tid * 4) = __ldg(pb + bn + tid);

    // resident B tile: [160 k-rows][128 n], hi/lo (n-contiguous for trans-ldmatrix)
    #pragma unroll
    for (int it = 0; it < 10; it++) {
        int idx = it * 256 + tid;            // 0..2559
        int k = idx >> 4, seg = idx & 15;    // seg: 8 bf16 = 16B
        const __nv_bfloat16* srch = g_Bh + (size_t)k * EOUT + bn + seg * 8;
        const __nv_bfloat16* srcl = g_Bl + (size_t)k * EOUT + bn + seg * 8;
        char* dst = smem + SM_B + k * BS_STRIDE + seg * 16;
        *(uint4*)dst = *(const uint4*)srch;
        *(uint4*)(dst + BS_SIZE) = *(const uint4*)srcl;
    }

    // A prefetch: thread t handles row r=t>>1, k-halfchunk (t&1)*16
    int ar = tid >> 1, ak = (tid & 1) * 16;
    uint4 pah[2], pal[2];
    {
        const __nv_bfloat16* sh = g_Sh + (size_t)(bm + ar) * KP + ak;
        const __nv_bfloat16* sl = g_Sl + (size_t)(bm + ar) * KP + ak;
        pah[0] = ((const uint4*)sh)[0]; pah[1] = ((const uint4*)sh)[1];
        pal[0] = ((const uint4*)sl)[0]; pal[1] = ((const uint4*)sl)[1];
    }

    auto sts_A = [&](int buf) {
        char* dst = smem + SM_A + buf * (2 * AS_SIZE) + ar * AS_STRIDE + ak * 2;
        *(uint4*)dst = pah[0];
        *(uint4*)(dst + 16) = pah[1];
        *(uint4*)(dst + AS_SIZE) = pal[0];
        *(uint4*)(dst + AS_SIZE + 16) = pal[1];
    };

    float acc[2][8][4];
    #pragma unroll
    for (int i = 0; i < 2; i++)
        #pragma unroll
        for (int j = 0; j < 8; j++)
            #pragma unroll
            for (int q = 0; q < 4; q++) acc[i][j][q] = 0.0f;

    sts_A(0);
    __syncthreads();

    // ldmatrix bases
    uint32_t a_base = sb + SM_A + (warp_m * 32 + (lane & 15)) * AS_STRIDE + (lane >> 4) * 16;
    // B trans: lanes 0-7 -> k rows 0-7, 8-15 -> k 8-15, 16-31 -> same k at n+8
    uint32_t b_base = sb + SM_B + ((lane & 7) + ((lane >> 3) & 1) * 8) * BS_STRIDE +
                      (warp_n * 64 + (lane >> 4) * 8) * 2;

    #pragma unroll 1
    for (int ch = 0; ch < NCHUNK; ch++) {
        int buf = ch & 1;
        if (ch < NCHUNK - 1) {
            const __nv_bfloat16* sh = g_Sh + (size_t)(bm + ar) * KP + (ch + 1) * KCH + ak;
            const __nv_bfloat16* sl = g_Sl + (size_t)(bm + ar) * KP + (ch + 1) * KCH + ak;
            pah[0] = ((const uint4*)sh)[0]; pah[1] = ((const uint4*)sh)[1];
            pal[0] = ((const uint4*)sl)[0]; pal[1] = ((const uint4*)sl)[1];
        }

        #pragma unroll
        for (int ks = 0; ks < 2; ks++) {
            uint32_t ah[2][4], al[2][4];
            #pragma unroll
            for (int mt = 0; mt < 2; mt++) {
                uint32_t aaddr = a_base + buf * (2 * AS_SIZE) + mt * 16 * AS_STRIDE + ks * 32;
                LDSM_X4(ah[mt], aaddr);
                LDSM_X4(al[mt], aaddr + AS_SIZE);
            }
            #pragma unroll
            for (int np = 0; np < 4; np++) {
                uint32_t baddr = b_base + (ch * KCH + ks * 16) * BS_STRIDE + np * 32;
                uint32_t bh[4], bl[4];
                LDSM_X4_T(bh, baddr);
                LDSM_X4_T(bl, baddr + BS_SIZE);
                #pragma unroll
                for (int mt = 0; mt < 2; mt++) {
                    #pragma unroll
                    for (int j = 0; j < 2; j++) {
                        float* d = acc[mt][np * 2 + j];
                        MMA_BF16(d, ah[mt], bh[j * 2], bh[j * 2 + 1]);
                        MMA_BF16(d, al[mt], bh[j * 2], bh[j * 2 + 1]);
                        MMA_BF16(d, ah[mt], bl[j * 2], bl[j * 2 + 1]);
                    }
                }
            }
        }

        if (ch < NCHUNK - 1) sts_A(1 - buf);
        __syncthreads();
    }

    // epilogue
    const float* sbias = (const float*)(smem + SM_BIAS);
    #pragma unroll
    for (int mt = 0; mt < 2; mt++) {
        int row0 = bm + warp_m * 32 + mt * 16 + (lane >> 2);
        #pragma unroll
        for (int nt = 0; nt < 8; nt++) {
            int cloc = warp_n * 64 + nt * 8 + (lane & 3) * 2;
            float b0 = sbias[cloc], b1 = sbias[cloc + 1];
            float* o0 = out + (size_t)row0 * EOUT + bn + cloc;
            float* o1 = o0 + 8 * EOUT;
            float2 v0 = {acc[mt][nt][0] + b0, acc[mt][nt][1] + b1};
            float2 v1 = {acc[mt][nt][2] + b0, acc[mt][nt][3] + b1};
            *(float2*)o0 = v0;
            *(float2*)o1 = v1;
        }
    }
}

extern "C" void kernel_launch(void* const* d_in, const int* in_sizes, int n_in,
                              void* d_out, int out_size)
{
    const float* x  = (const float*)d_in[0];
    const float* mw = (const float*)d_in[1];
    const float* mb = (const float*)d_in[2];
    const float* pw = (const float*)d_in[3];
    const float* pb = (const float*)d_in[4];
    float* out = (float*)d_out;

    cudaFuncSetAttribute(gemm_mma, cudaFuncAttributeMaxDynamicSharedMemorySize, SMEM_TOTAL);

    init_dirs_kernel<<<1, 64>>>();
    bfill_kernel<<<(KP * EOUT + 255) / 256, 256>>>(pw);
    sample_kernel<<<NPATCH / 8, 256>>>(x, mw, mb);
    gemm_mma<<<dim3(NMT, EOUT / NT), 256, SMEM_TOTAL>>>(pb, out);
}

// round 6
// speedup vs baseline: 1.9802x; 1.0465x over previous
#include <cuda_runtime.h>
#include <cuda_bf16.h>
#include <math.h>
#include <stdint.h>

#define NDIR 49
#define KDIM 147
#define KP 160            // K padded to 5 x 32 chunks
#define NPATCH 65536      // 64 * 32 * 32
#define EOUT 384
#define HW 224
#define MT 128
#define NT 128
#define NMT (NPATCH / MT) // 512
#define KCH 32
#define NCHUNK (KP / KCH) // 5

// SMEM per buffer (bytes):
//   A_hi [128 x 80B], A_lo, B_hi [32 x 272B], B_lo
#define AS_STRIDE 80
#define AS_PLANE  (128 * AS_STRIDE)   // 10240
#define BS_STRIDE 272
#define BS_PLANE  (KCH * BS_STRIDE)   // 8704
#define OFF_AH 0
#define OFF_AL AS_PLANE
#define OFF_BH (2 * AS_PLANE)
#define OFF_BL (2 * AS_PLANE + BS_PLANE)
#define BUFSZ  (2 * AS_PLANE + 2 * BS_PLANE)  // 37888
#define SMEM_TOTAL (2 * BUFSZ)                 // 75776

// ---- scratch ----
__device__ __align__(16) __nv_bfloat16 g_Sh[(size_t)NPATCH * KP];
__device__ __align__(16) __nv_bfloat16 g_Sl[(size_t)NPATCH * KP];
__device__ __align__(16) __nv_bfloat16 g_Bh[KP * EOUT];  // [k][e]
__device__ __align__(16) __nv_bfloat16 g_Bl[KP * EOUT];
__device__ float g_u0[NDIR], g_u1[NDIR], g_sv[NDIR];

__device__ __forceinline__ float sigf(float v) { return 1.0f / (1.0f + expf(-v)); }

__device__ __forceinline__ uint32_t smem_u32(const void* p) {
    uint32_t a;
    asm("{ .reg .u64 t; cvta.to.shared.u64 t, %1; cvt.u32.u64 %0, t; }" : "=r"(a) : "l"(p));
    return a;
}

__device__ __forceinline__ void cp16(uint32_t dst, const void* src) {
    asm volatile("cp.async.cg.shared.global [%0], [%1], 16;" :: "r"(dst), "l"(src));
}

#define LDSM_X4(r, addr) \
    asm volatile("ldmatrix.sync.aligned.m8n8.x4.shared.b16 {%0,%1,%2,%3}, [%4];" \
        : "=r"((r)[0]), "=r"((r)[1]), "=r"((r)[2]), "=r"((r)[3]) : "r"(addr))

#define LDSM_X4_T(r, addr) \
    asm volatile("ldmatrix.sync.aligned.m8n8.x4.trans.shared.b16 {%0,%1,%2,%3}, [%4];" \
        : "=r"((r)[0]), "=r"((r)[1]), "=r"((r)[2]), "=r"((r)[3]) : "r"(addr))

#define MMA_BF16(d, a, b0, b1) \
    asm volatile("mma.sync.aligned.m16n8k16.row.col.f32.bf16.bf16.f32 " \
        "{%0,%1,%2,%3}, {%4,%5,%6,%7}, {%8,%9}, {%0,%1,%2,%3};" \
        : "+f"((d)[0]), "+f"((d)[1]), "+f"((d)[2]), "+f"((d)[3]) \
        : "r"((a)[0]), "r"((a)[1]), "r"((a)[2]), "r"((a)[3]), "r"(b0), "r"(b1))

__device__ __forceinline__ void split_bf(float v, __nv_bfloat16& h, __nv_bfloat16& l) {
    h = __float2bfloat16_rn(v);
    l = __float2bfloat16_rn(v - __bfloat162float(h));
}

// ---------------- init: direction table ----------------
__global__ void init_dirs_kernel() {
    int n = threadIdx.x;
    if (n >= NDIR) return;
    float u0, u1, sv;
    if (n == 0) { u0 = 1.f; u1 = 0.f; sv = 0.f; }
    else {
        int k, nk, m;
        if (n < 9)       { k = 1; nk = 8;  m = n - 1;  }
        else if (n < 25) { k = 2; nk = 16; m = n - 9;  }
        else             { k = 3; nk = 24; m = n - 25; }
        double th = 2.0 * 3.14159265358979323846 * (double)m / (double)nk;
        u0 = (float)cos(th); u1 = (float)sin(th);
        sv = (float)((double)k / 3.0);
    }
    g_u0[n] = u0; g_u1[n] = u1; g_sv[n] = sv;
}

// -------- prep: proj_w -> transposed, padded, hi/lo bf16 [k][e] --------
__global__ void bfill_kernel(const float* __restrict__ pw) {
    int idx = blockIdx.x * blockDim.x + threadIdx.x;
    if (idx >= KP * EOUT) return;
    int k = idx / EOUT, e = idx % EOUT;
    float v = (k < KDIM) ? pw[e * KDIM + k] : 0.0f;
    __nv_bfloat16 h, l;
    split_bf(v, h, l);
    g_Bh[idx] = h;
    g_Bl[idx] = l;
}

// ---------------- stage A: params + sampling ----------------
__global__ __launch_bounds__(256) void sample_kernel(
    const float* __restrict__ x, const float* __restrict__ mw, const float* __restrict__ mb)
{
    __shared__ float s_w[7 * KDIM];
    __shared__ float s_px[8][KDIM + 1];
    __shared__ float s_d[8][8];

    int t = threadIdx.x;
    for (int i = t; i < 7 * KDIM; i += 256) s_w[i] = mw[i];

    int warp = t >> 5, lane = t & 31;
    int p = blockIdx.x * 8 + warp;
    int b = p >> 10;
    int rem = p & 1023;
    int hp = rem >> 5, wp = rem & 31;
    const float* xb = x + (size_t)b * 3 * HW * HW;

    for (int idx = lane; idx < KDIM; idx += 32) {
        int c = idx / 49, r2 = idx % 49, i = r2 / 7, j = r2 % 7;
        s_px[warp][idx] = __ldg(xb + ((size_t)c * HW + hp * 7 + i) * HW + wp * 7 + j);
    }
    __syncthreads();

    float acc[7] = {0.f,0.f,0.f,0.f,0.f,0.f,0.f};
    for (int idx = lane; idx < KDIM; idx += 32) {
        float v = s_px[warp][idx];
        #pragma unroll
        for (int f = 0; f < 7; f++) acc[f] += v * s_w[f * KDIM + idx];
    }
    #pragma unroll
    for (int f = 0; f < 7; f++) {
        #pragma unroll
        for (int off = 16; off > 0; off >>= 1)
            acc[f] += __shfl_down_sync(0xffffffffu, acc[f], off);
    }

    if (lane == 0) {
        float q0 = acc[0] + __ldg(mb + 0);
        float q1 = acc[1] + __ldg(mb + 1);
        float q2 = acc[2] + __ldg(mb + 2);
        float q3 = acc[3] + __ldg(mb + 3);
        float q4 = acc[4] + __ldg(mb + 4);
        float q5 = acc[5] + __ldg(mb + 5);
        float q6 = acc[6] + __ldg(mb + 6);
        float nrm = fmaxf(sqrtf(q0*q0 + q1*q1), 1e-12f);
        float v0 = q0 / nrm, v1 = q1 / nrm;
        float sc = 0.5f + 1.5f * sigf(q4);
        float e0 = 2.0f * sigf(q2) * sc;
        float e1 = 2.0f * sigf(q3) * sc;
        float m00 = e0 * v0 * v0 + e1 * v1 * v1;
        float m01 = (e0 - e1) * v0 * v1;
        float m11 = e0 * v1 * v1 + e1 * v0 * v0;
        float wn = sqrtf(q5*q5 + q6*q6);
        float ws = 0.5f * sigf(wn);
        s_d[warp][0] = m00; s_d[warp][1] = m01; s_d[warp][2] = m11;
        s_d[warp][3] = q5 * ws; s_d[warp][4] = q6 * ws;
    }
    __syncwarp();

    float m00 = s_d[warp][0], m01 = s_d[warp][1], m11 = s_d[warp][2];
    float w0 = s_d[warp][3], w1 = s_d[warp][4];
    float cy = (float)(hp * 7 + 3);
    float cx = (float)(wp * 7 + 3);
    size_t rbase = (size_t)p * KP;

    for (int n = lane; n < NDIR; n += 32) {
        float u0 = g_u0[n], u1 = g_u1[n], sv = g_sv[n];
        float quad = u0*u0*m00 + 2.0f*u0*u1*m01 + u1*u1*m11;
        float F = sqrtf(quad + 1e-6f) + w0 * u0 + w1 * u1;
        float tt = sv / (F + 1e-6f);
        float py = u1 * tt + cy;
        float px = u0 * tt + cx;
        float y0 = floorf(py), x0 = floorf(px);
        float wy = py - y0, wx = px - x0;

        float s0 = 0.f, s1 = 0.f, s2 = 0.f;
        #pragma unroll
        for (int corner = 0; corner < 4; corner++) {
            float yf = y0 + (float)(corner >> 1);
            float xf = x0 + (float)(corner & 1);
            float wgt = ((corner >> 1) ? wy : (1.0f - wy)) * ((corner & 1) ? wx : (1.0f - wx));
            bool valid = (yf >= 0.f) && (yf <= 223.f) && (xf >= 0.f) && (xf <= 223.f);
            if (valid) {
                int yi = (int)yf, xi = (int)xf;
                const float* ptr = xb + (size_t)yi * HW + xi;
                s0 += wgt * __ldg(ptr);
                s1 += wgt * __ldg(ptr + HW * HW);
                s2 += wgt * __ldg(ptr + 2 * HW * HW);
            }
        }
        __nv_bfloat16 h, l;
        split_bf(s0, h, l); g_Sh[rbase + 0 * 49 + n] = h; g_Sl[rbase + 0 * 49 + n] = l;
        split_bf(s1, h, l); g_Sh[rbase + 1 * 49 + n] = h; g_Sl[rbase + 1 * 49 + n] = l;
        split_bf(s2, h, l); g_Sh[rbase + 2 * 49 + n] = h; g_Sl[rbase + 2 * 49 + n] = l;
    }
    if (lane < KP - KDIM) {
        g_Sh[rbase + KDIM + lane] = __float2bfloat16(0.0f);
        g_Sl[rbase + KDIM + lane] = __float2bfloat16(0.0f);
    }
}

// ---------------- stage B: bf16 mma.sync 3-product GEMM, cp.async ----------
__global__ void __launch_bounds__(256)
gemm_mma(const float* __restrict__ pb, float* __restrict__ out)
{
    extern __shared__ __align__(16) char smem[];
    uint32_t sb = smem_u32(smem);
    int tid = threadIdx.x, wid = tid >> 5, lane = tid & 31;
    int warp_m = wid & 3, warp_n = wid >> 2;
    int bm = blockIdx.x * MT;
    int bn = blockIdx.y * NT;

    // async-load one 32-k chunk (A hi/lo + B hi/lo) into buffer `buf`
    auto issue_chunk = [&](int ch, int buf) {
        uint32_t bb = sb + buf * BUFSZ;
        // A: 128 rows x 4 segs (16B) per plane
        #pragma unroll
        for (int i = 0; i < 2; i++) {
            int idx = i * 256 + tid;
            int r = idx >> 2, seg = idx & 3;
            size_t goff = (size_t)(bm + r) * KP + ch * KCH + seg * 8;
            cp16(bb + OFF_AH + r * AS_STRIDE + seg * 16, g_Sh + goff);
            cp16(bb + OFF_AL + r * AS_STRIDE + seg * 16, g_Sl + goff);
        }
        // B: 32 k-rows x 16 segs (16B) per plane
        #pragma unroll
        for (int i = 0; i < 2; i++) {
            int idx = i * 256 + tid;
            int r = idx >> 4, seg = idx & 15;
            size_t goff = (size_t)(ch * KCH + r) * EOUT + bn + seg * 8;
            cp16(bb + OFF_BH + r * BS_STRIDE + seg * 16, g_Bh + goff);
            cp16(bb + OFF_BL + r * BS_STRIDE + seg * 16, g_Bl + goff);
        }
        asm volatile("cp.async.commit_group;" ::: "memory");
    };

    float acc[2][8][4];
    #pragma unroll
    for (int i = 0; i < 2; i++)
        #pragma unroll
        for (int j = 0; j < 8; j++)
            #pragma unroll
            for (int q = 0; q < 4; q++) acc[i][j][q] = 0.0f;

    issue_chunk(0, 0);

    // ldmatrix base addresses (buffer-relative)
    uint32_t a_off = (uint32_t)((warp_m * 32 + (lane & 15)) * AS_STRIDE + (lane >> 4) * 16);
    uint32_t b_off = (uint32_t)(OFF_BH + ((lane & 7) + ((lane >> 3) & 1) * 8) * BS_STRIDE +
                                (warp_n * 64 + (lane >> 4) * 8) * 2);

    #pragma unroll 1
    for (int ch = 0; ch < NCHUNK; ch++) {
        int buf = ch & 1;
        asm volatile("cp.async.wait_group 0;" ::: "memory");
        __syncthreads();
        if (ch + 1 < NCHUNK) issue_chunk(ch + 1, 1 - buf);

        uint32_t bb = sb + buf * BUFSZ;
        #pragma unroll
        for (int ks = 0; ks < 2; ks++) {
            uint32_t ah[2][4], al[2][4];
            #pragma unroll
            for (int mt = 0; mt < 2; mt++) {
                uint32_t aaddr = bb + a_off + mt * 16 * AS_STRIDE + ks * 32;
                LDSM_X4(ah[mt], aaddr);
                LDSM_X4(al[mt], aaddr + AS_PLANE);
            }
            #pragma unroll
            for (int np = 0; np < 4; np++) {
                uint32_t baddr = bb + b_off + ks * 16 * BS_STRIDE + np * 32;
                uint32_t bh[4], bl[4];
                LDSM_X4_T(bh, baddr);
                LDSM_X4_T(bl, baddr + BS_PLANE);
                #pragma unroll
                for (int mt = 0; mt < 2; mt++) {
                    #pragma unroll
                    for (int j = 0; j < 2; j++) {
                        float* d = acc[mt][np * 2 + j];
                        MMA_BF16(d, ah[mt], bh[j * 2], bh[j * 2 + 1]);
                        MMA_BF16(d, al[mt], bh[j * 2], bh[j * 2 + 1]);
                        MMA_BF16(d, ah[mt], bl[j * 2], bl[j * 2 + 1]);
                    }
                }
            }
        }
        __syncthreads();
    }

    // epilogue
    #pragma unroll
    for (int mt = 0; mt < 2; mt++) {
        int row0 = bm + warp_m * 32 + mt * 16 + (lane >> 2);
        #pragma unroll
        for (int nt = 0; nt < 8; nt++) {
            int cloc = warp_n * 64 + nt * 8 + (lane & 3) * 2;
            float b0 = __ldg(pb + bn + cloc);
            float b1 = __ldg(pb + bn + cloc + 1);
            float* o0 = out + (size_t)row0 * EOUT + bn + cloc;
            float* o1 = o0 + 8 * EOUT;
            float2 v0 = {acc[mt][nt][0] + b0, acc[mt][nt][1] + b1};
            float2 v1 = {acc[mt][nt][2] + b0, acc[mt][nt][3] + b1};
            *(float2*)o0 = v0;
            *(float2*)o1 = v1;
        }
    }
}

extern "C" void kernel_launch(void* const* d_in, const int* in_sizes, int n_in,
                              void* d_out, int out_size)
{
    const float* x  = (const float*)d_in[0];
    const float* mw = (const float*)d_in[1];
    const float* mb = (const float*)d_in[2];
    const float* pw = (const float*)d_in[3];
    const float* pb = (const float*)d_in[4];
    float* out = (float*)d_out;

    cudaFuncSetAttribute(gemm_mma, cudaFuncAttributeMaxDynamicSharedMemorySize, SMEM_TOTAL);

    init_dirs_kernel<<<1, 64>>>();
    bfill_kernel<<<(KP * EOUT + 255) / 256, 256>>>(pw);
    sample_kernel<<<NPATCH / 8, 256>>>(x, mw, mb);
    gemm_mma<<<dim3(NMT, EOUT / NT), 256, SMEM_TOTAL>>>(pb, out);
}